// round 1
// baseline (speedup 1.0000x reference)
#include <cuda_runtime.h>
#include <cstdint>
#include <cstddef>

#define MAXN 100000
#define NI   1024

// Scratch (allocation-free rule: __device__ globals). Ping-pong roles:
//   prep  : writes g_bufX (LN1+lrelu of gram)
//   gemm1 : reads g_bufX, writes g_bufH
//   ln2   : reads g_bufH, writes g_bufX
//   gemm2 : reads g_bufX, writes g_bufH
//   post  : reads g_bufH
__device__ float g_bufX[(size_t)MAXN * NI];
__device__ float g_bufH[(size_t)MAXN * NI];

// ---------------------------------------------------------------- utilities

__device__ __forceinline__ void split_tf32(float x, uint32_t& hi, uint32_t& lo)
{
    uint32_t h;
    asm("cvt.rna.tf32.f32 %0, %1;" : "=r"(h) : "f"(x));
    float r = x - __uint_as_float(h);
    uint32_t l;
    asm("cvt.rna.tf32.f32 %0, %1;" : "=r"(l) : "f"(r));
    hi = h; lo = l;
}

__device__ __forceinline__ void mma_tf32(float* c, const uint32_t* a, const uint32_t* b)
{
    asm volatile(
        "mma.sync.aligned.m16n8k8.row.col.f32.tf32.tf32.f32 "
        "{%0,%1,%2,%3}, {%4,%5,%6,%7}, {%8,%9}, {%0,%1,%2,%3};\n"
        : "+f"(c[0]), "+f"(c[1]), "+f"(c[2]), "+f"(c[3])
        : "r"(a[0]), "r"(a[1]), "r"(a[2]), "r"(a[3]),
          "r"(b[0]), "r"(b[1]));
}

// Block-wide mean / rstd over NI=1024 values, one value per thread (1024 thr).
__device__ __forceinline__ void block_stats(float v, float* red, float& mu, float& rstd)
{
    float s1 = v, s2 = v * v;
    #pragma unroll
    for (int off = 16; off > 0; off >>= 1) {
        s1 += __shfl_xor_sync(0xffffffffu, s1, off);
        s2 += __shfl_xor_sync(0xffffffffu, s2, off);
    }
    int wid = threadIdx.x >> 5, lane = threadIdx.x & 31;
    if (lane == 0) { red[wid] = s1; red[32 + wid] = s2; }
    __syncthreads();
    if (wid == 0) {
        s1 = red[lane]; s2 = red[32 + lane];
        #pragma unroll
        for (int off = 16; off > 0; off >>= 1) {
            s1 += __shfl_xor_sync(0xffffffffu, s1, off);
            s2 += __shfl_xor_sync(0xffffffffu, s2, off);
        }
        if (lane == 0) { red[0] = s1; red[32] = s2; }
    }
    __syncthreads();
    float mean = red[0] * (1.0f / NI);
    float var  = red[32] * (1.0f / NI) - mean * mean;
    mu = mean;
    rstd = rsqrtf(var + 1e-5f);
}

// ---------------------------------------------------------------- stage 1
// Per node: gram = v@v^T, sign-clamp, LayerNorm(g1,b1), leaky-relu -> g_bufX.
__global__ void prep_kernel(const float* __restrict__ f,
                            const float* __restrict__ gamma,
                            const float* __restrict__ beta,
                            int m)
{
    int n = blockIdx.x;
    __shared__ float sv[96];
    __shared__ float red[64];
    int t = threadIdx.x;                  // 0..1023 == a*32+b
    if (t < 32 * m) sv[t] = f[(size_t)n * 32 * m + t];
    __syncthreads();
    int a = t >> 5, b = t & 31;
    float d = 0.f;
    #pragma unroll 3
    for (int c = 0; c < m; ++c) d += sv[a * m + c] * sv[b * m + c];
    // sign(d) * max(|d|, 1e-12)  (exact-zero stays zero, matching jnp.sign)
    if (d > 0.f)      d = fmaxf(d,  1e-12f);
    else if (d < 0.f) d = fminf(d, -1e-12f);
    float mu, rstd;
    block_stats(d, red, mu, rstd);
    float y = (d - mu) * rstd * gamma[t] + beta[t];
    y = (y >= 0.f) ? y : 0.01f * y;
    g_bufX[(size_t)n * NI + t] = y;
}

// ---------------------------------------------------------------- stage 3
// LayerNorm(g2,b2) + leaky-relu on g_bufH -> g_bufX.
__global__ void mid_ln_kernel(const float* __restrict__ gamma,
                              const float* __restrict__ beta)
{
    int n = blockIdx.x;
    int t = threadIdx.x;
    __shared__ float red[64];
    float d = g_bufH[(size_t)n * NI + t];
    float mu, rstd;
    block_stats(d, red, mu, rstd);
    float y = (d - mu) * rstd * gamma[t] + beta[t];
    y = (y >= 0.f) ? y : 0.01f * y;
    g_bufX[(size_t)n * NI + t] = y;
}

// ---------------------------------------------------------------- GEMM
// C[M,1024] = A[M,1024] @ W[1024,1024]^T (+bias), A=g_bufX, C=g_bufH.
// 3xTF32 split products for ~fp32 accuracy. 128x128x32 tile, 8 warps (64x32).
__global__ __launch_bounds__(256)
void gemm3x_kernel(const float* __restrict__ W,
                   const float* __restrict__ bias,
                   int M)
{
    __shared__ float As[128 * 36];
    __shared__ float Bs[128 * 36];

    const int tid    = threadIdx.x;
    const int wid    = tid >> 5;
    const int lane   = tid & 31;
    const int warp_m = wid >> 2;          // 0..1  (64 rows each)
    const int warp_n = wid & 3;           // 0..3  (32 cols each)
    const int g      = lane >> 2;         // 0..7
    const int tg     = lane & 3;          // 0..3
    const int bm     = blockIdx.x * 128;
    const int bn     = blockIdx.y * 128;

    float acc[4][4][4];
    #pragma unroll
    for (int i = 0; i < 4; ++i)
        #pragma unroll
        for (int j = 0; j < 4; ++j)
            #pragma unroll
            for (int k = 0; k < 4; ++k) acc[i][j][k] = 0.f;

    const int lr = tid >> 1;              // 0..127
    const int lk = (tid & 1) * 16;        // 0 or 16
    const float* gA = g_bufX + (size_t)(bm + lr) * NI + lk;
    const float* gB = W      + (size_t)(bn + lr) * NI + lk;
    const bool avalid = (bm + lr) < M;

    for (int kc = 0; kc < NI; kc += 32) {
        #pragma unroll
        for (int i = 0; i < 4; ++i) {
            float4 va = avalid ? *(const float4*)(gA + kc + i * 4)
                               : make_float4(0.f, 0.f, 0.f, 0.f);
            *(float4*)(&As[lr * 36 + lk + i * 4]) = va;
            float4 vb = *(const float4*)(gB + kc + i * 4);
            *(float4*)(&Bs[lr * 36 + lk + i * 4]) = vb;
        }
        __syncthreads();
        #pragma unroll
        for (int ks = 0; ks < 4; ++ks) {
            const int kk = ks * 8;
            uint32_t ah[4][4], al[4][4];
            #pragma unroll
            for (int i = 0; i < 4; ++i) {
                int row = warp_m * 64 + i * 16 + g;
                float a0 = As[row * 36 + kk + tg];
                float a1 = As[(row + 8) * 36 + kk + tg];
                float a2 = As[row * 36 + kk + tg + 4];
                float a3 = As[(row + 8) * 36 + kk + tg + 4];
                split_tf32(a0, ah[i][0], al[i][0]);
                split_tf32(a1, ah[i][1], al[i][1]);
                split_tf32(a2, ah[i][2], al[i][2]);
                split_tf32(a3, ah[i][3], al[i][3]);
            }
            uint32_t bh[4][2], bl[4][2];
            #pragma unroll
            for (int j = 0; j < 4; ++j) {
                int col = warp_n * 32 + j * 8 + g;
                float b0 = Bs[col * 36 + kk + tg];
                float b1 = Bs[col * 36 + kk + tg + 4];
                split_tf32(b0, bh[j][0], bl[j][0]);
                split_tf32(b1, bh[j][1], bl[j][1]);
            }
            #pragma unroll
            for (int i = 0; i < 4; ++i)
                #pragma unroll
                for (int j = 0; j < 4; ++j) {
                    mma_tf32(acc[i][j], ah[i], bh[j]);   // hi*hi
                    mma_tf32(acc[i][j], al[i], bh[j]);   // lo*hi
                    mma_tf32(acc[i][j], ah[i], bl[j]);   // hi*lo
                }
        }
        __syncthreads();
    }

    #pragma unroll
    for (int i = 0; i < 4; ++i) {
        int row0 = bm + warp_m * 64 + i * 16 + g;
        #pragma unroll
        for (int j = 0; j < 4; ++j) {
            int col = bn + warp_n * 32 + j * 8 + tg * 2;
            float b0 = bias ? bias[col]     : 0.f;
            float b1 = bias ? bias[col + 1] : 0.f;
            if (row0 < M) {
                g_bufH[(size_t)row0 * NI + col]     = acc[i][j][0] + b0;
                g_bufH[(size_t)row0 * NI + col + 1] = acc[i][j][1] + b1;
            }
            if (row0 + 8 < M) {
                g_bufH[(size_t)(row0 + 8) * NI + col]     = acc[i][j][2] + b0;
                g_bufH[(size_t)(row0 + 8) * NI + col + 1] = acc[i][j][3] + b1;
            }
        }
    }
}

// ---------------------------------------------------------------- stage 5
// softmax over ci (warp = one output channel), out = attn @ v.
__global__ void post_kernel(const float* __restrict__ f,
                            float* __restrict__ out,
                            int m)
{
    int n = blockIdx.x;
    __shared__ float sv[96];
    int t = threadIdx.x;
    if (t < 32 * m) sv[t] = f[(size_t)n * 32 * m + t];
    __syncthreads();
    int o = t >> 5, lane = t & 31;
    float l = g_bufH[(size_t)n * NI + o * 32 + lane];
    float mx = l;
    #pragma unroll
    for (int off = 16; off > 0; off >>= 1)
        mx = fmaxf(mx, __shfl_xor_sync(0xffffffffu, mx, off));
    float e = expf(l - mx);
    float s = e;
    #pragma unroll
    for (int off = 16; off > 0; off >>= 1)
        s += __shfl_xor_sync(0xffffffffu, s, off);
    float attn = e / s;
    #pragma unroll 3
    for (int c = 0; c < m; ++c) {
        float p = attn * sv[lane * m + c];
        #pragma unroll
        for (int off = 16; off > 0; off >>= 1)
            p += __shfl_xor_sync(0xffffffffu, p, off);
        if (lane == 0) out[(size_t)n * 32 * m + o * m + c] = p;
    }
}

// ---------------------------------------------------------------- launch

static void run_type(const float* f, void* const* prm, float* out, int N, int m)
{
    const float* g1    = (const float*)prm[0];
    const float* b1    = (const float*)prm[1];
    const float* w1    = (const float*)prm[2];
    const float* g2    = (const float*)prm[3];
    const float* b2    = (const float*)prm[4];
    const float* w2    = (const float*)prm[5];
    const float* bias2 = (const float*)prm[6];

    prep_kernel<<<N, 1024>>>(f, g1, b1, m);
    dim3 grid((N + 127) / 128, NI / 128);
    gemm3x_kernel<<<grid, 256>>>(w1, nullptr, N);
    mid_ln_kernel<<<N, 1024>>>(g2, b2);
    gemm3x_kernel<<<grid, 256>>>(w2, bias2, N);
    post_kernel<<<N, 1024>>>(f, out, m);
}

extern "C" void kernel_launch(void* const* d_in, const int* in_sizes, int n_in,
                              void* d_out, int out_size)
{
    const float* f0 = (const float*)d_in[0];
    const float* f1 = (const float*)d_in[1];
    int N0 = in_sizes[0] / 32;   // f0: [N,32,1]
    int N1 = in_sizes[1] / 96;   // f1: [N,32,3]
    if (N0 > MAXN) N0 = MAXN;
    if (N1 > MAXN) N1 = MAXN;
    float* out = (float*)d_out;

    run_type(f0, d_in + 2, out, N0, 1);                       // out0: N0*32 floats
    run_type(f1, d_in + 9, out + (size_t)N0 * 32, N1, 3);     // out1: N1*96 floats
}

// round 3
// speedup vs baseline: 1.4841x; 1.4841x over previous
#include <cuda_runtime.h>
#include <cuda_bf16.h>
#include <cstdint>
#include <cstddef>

#define MAXN 100000
#define MPAD 100096            // MAXN rounded up to 128
#define NI   1024

#define BM   128
#define BN   128
#define BK   32
#define NCH  (NI / BK)         // 32 chunks
#define NSTG 3

// smem tile: [128 rows][40 bf16] (32 data + 8 pad) = 10240 B
#define TILE_B   10240
#define ROW_B    80
#define OFF_AHI  0
#define OFF_ALO  (1 * TILE_B)
#define OFF_BHI  (2 * TILE_B)
#define OFF_BLO  (3 * TILE_B)
#define STAGE_B  (4 * TILE_B)          // 40960
#define DYN_SMEM (NSTG * STAGE_B)      // 122880

// ---------------------------------------------------------------- scratch
__device__ __nv_bfloat16 g_Xhi[(size_t)MPAD * NI];   // zero-init: rows >= M stay 0
__device__ __nv_bfloat16 g_Xlo[(size_t)MPAD * NI];
__device__ float         g_bufH[(size_t)MPAD * NI];
__device__ __nv_bfloat16 g_Whi[(size_t)NI * NI];
__device__ __nv_bfloat16 g_Wlo[(size_t)NI * NI];

// ---------------------------------------------------------------- PTX utils
__device__ __forceinline__ uint32_t smem_u32(const void* p)
{
    uint32_t a;
    asm("{ .reg .u64 t; cvta.to.shared.u64 t, %1; cvt.u32.u64 %0, t; }"
        : "=r"(a) : "l"(p));
    return a;
}

#define LDSM_X4(r, addr)                                                        \
    asm volatile("ldmatrix.sync.aligned.m8n8.x4.shared.b16 {%0,%1,%2,%3}, [%4];"\
        : "=r"((r)[0]), "=r"((r)[1]), "=r"((r)[2]), "=r"((r)[3]) : "r"(addr))

__device__ __forceinline__ void mma_bf16(float* c, const uint32_t* a,
                                         const uint32_t b0, const uint32_t b1)
{
    asm volatile(
        "mma.sync.aligned.m16n8k16.row.col.f32.bf16.bf16.f32 "
        "{%0,%1,%2,%3}, {%4,%5,%6,%7}, {%8,%9}, {%0,%1,%2,%3};\n"
        : "+f"(c[0]), "+f"(c[1]), "+f"(c[2]), "+f"(c[3])
        : "r"(a[0]), "r"(a[1]), "r"(a[2]), "r"(a[3]), "r"(b0), "r"(b1));
}

// ---------------------------------------------------------------- LN stats
__device__ __forceinline__ void block_stats(float v, float* red, float& mu, float& rstd)
{
    float s1 = v, s2 = v * v;
    #pragma unroll
    for (int off = 16; off > 0; off >>= 1) {
        s1 += __shfl_xor_sync(0xffffffffu, s1, off);
        s2 += __shfl_xor_sync(0xffffffffu, s2, off);
    }
    int wid = threadIdx.x >> 5, lane = threadIdx.x & 31;
    if (lane == 0) { red[wid] = s1; red[32 + wid] = s2; }
    __syncthreads();
    if (wid == 0) {
        s1 = red[lane]; s2 = red[32 + lane];
        #pragma unroll
        for (int off = 16; off > 0; off >>= 1) {
            s1 += __shfl_xor_sync(0xffffffffu, s1, off);
            s2 += __shfl_xor_sync(0xffffffffu, s2, off);
        }
        if (lane == 0) { red[0] = s1; red[32] = s2; }
    }
    __syncthreads();
    float mean = red[0] * (1.0f / NI);
    float var  = red[32] * (1.0f / NI) - mean * mean;
    mu = mean;
    rstd = rsqrtf(var + 1e-5f);
}

__device__ __forceinline__ void split_store(size_t idx, float y)
{
    __nv_bfloat16 h = __float2bfloat16_rn(y);
    g_Xhi[idx] = h;
    g_Xlo[idx] = __float2bfloat16_rn(y - __bfloat162float(h));
}

// ---------------------------------------------------------------- stage 1
// Gram + sign-clamp + LN1 + lrelu -> bf16 hi/lo split
__global__ void prep_kernel(const float* __restrict__ f,
                            const float* __restrict__ gamma,
                            const float* __restrict__ beta,
                            int m)
{
    int n = blockIdx.x;
    __shared__ float sv[96];
    __shared__ float red[64];
    int t = threadIdx.x;
    if (t < 32 * m) sv[t] = f[(size_t)n * 32 * m + t];
    __syncthreads();
    int a = t >> 5, b = t & 31;
    float d = 0.f;
    #pragma unroll 3
    for (int c = 0; c < m; ++c) d += sv[a * m + c] * sv[b * m + c];
    if (d > 0.f)      d = fmaxf(d,  1e-12f);
    else if (d < 0.f) d = fminf(d, -1e-12f);
    float mu, rstd;
    block_stats(d, red, mu, rstd);
    float y = (d - mu) * rstd * gamma[t] + beta[t];
    y = (y >= 0.f) ? y : 0.01f * y;
    split_store((size_t)n * NI + t, y);
}

// ---------------------------------------------------------------- stage 3
__global__ void mid_ln_kernel(const float* __restrict__ gamma,
                              const float* __restrict__ beta)
{
    int n = blockIdx.x;
    int t = threadIdx.x;
    __shared__ float red[64];
    float d = g_bufH[(size_t)n * NI + t];
    float mu, rstd;
    block_stats(d, red, mu, rstd);
    float y = (d - mu) * rstd * gamma[t] + beta[t];
    y = (y >= 0.f) ? y : 0.01f * y;
    split_store((size_t)n * NI + t, y);
}

// ---------------------------------------------------------------- W split
__global__ void splitw_kernel(const float* __restrict__ W)
{
    int i = blockIdx.x * 256 + threadIdx.x;
    float w = W[i];
    __nv_bfloat16 h = __float2bfloat16_rn(w);
    g_Whi[i] = h;
    g_Wlo[i] = __float2bfloat16_rn(w - __bfloat162float(h));
}

// ---------------------------------------------------------------- GEMM
// C[M,1024] = X @ W^T (+bias), bf16x3 split (hh + lh + hl), HMMA m16n8k16.
// 128x128x32 tile, 8 warps (warp 64x32), 3-stage cp.async pipeline.
__device__ __forceinline__ void load_stage(uint32_t sbase, int bm, int bn,
                                           int k0, int tid)
{
    #pragma unroll 8
    for (int i = 0; i < 8; ++i) {
        int idx  = tid + i * 256;          // 0..2047
        int tile = idx >> 9;               // 0..3
        int r    = (idx >> 2) & 127;
        int c    = (idx & 3) * 8;          // bf16 col
        const __nv_bfloat16* src;
        if (tile < 2)
            src = ((tile == 0) ? g_Xhi : g_Xlo) + (size_t)(bm + r) * NI + k0 + c;
        else
            src = ((tile == 2) ? g_Whi : g_Wlo) + (size_t)(bn + r) * NI + k0 + c;
        uint32_t dst = sbase + tile * TILE_B + r * ROW_B + c * 2;
        asm volatile("cp.async.cg.shared.global [%0], [%1], 16;"
                     :: "r"(dst), "l"(src) : "memory");
    }
    asm volatile("cp.async.commit_group;" ::: "memory");
}

__global__ __launch_bounds__(256)
void gemm_bf16_kernel(const float* __restrict__ bias, int M)
{
    extern __shared__ __align__(128) char dyn[];

    const int tid    = threadIdx.x;
    const int wid    = tid >> 5;
    const int lane   = tid & 31;
    const int warp_m = wid >> 2;           // 0..1
    const int warp_n = wid & 3;            // 0..3
    const int bn     = blockIdx.x * BN;
    const int bm     = blockIdx.y * BM;

    const uint32_t sdyn = smem_u32(dyn);

    // ldmatrix per-lane byte offsets
    const uint32_t laneA = (uint32_t)((lane & 15) * ROW_B + (lane >> 4) * 16);
    const uint32_t laneB = (uint32_t)(((lane & 7) + ((lane >> 4) * 8)) * ROW_B
                                      + (((lane >> 3) & 1) * 16));
    const uint32_t aWarp = (uint32_t)(warp_m * 64 * ROW_B);
    const uint32_t bWarp = (uint32_t)(warp_n * 32 * ROW_B);

    float acc[4][4][4];
    #pragma unroll
    for (int i = 0; i < 4; ++i)
        #pragma unroll
        for (int j = 0; j < 4; ++j)
            #pragma unroll
            for (int k = 0; k < 4; ++k) acc[i][j][k] = 0.f;

    load_stage(sdyn + 0 * STAGE_B, bm, bn, 0 * BK, tid);
    load_stage(sdyn + 1 * STAGE_B, bm, bn, 1 * BK, tid);
    load_stage(sdyn + 2 * STAGE_B, bm, bn, 2 * BK, tid);

    int stage = 0;
    for (int c = 0; c < NCH; ++c) {
        asm volatile("cp.async.wait_group 2;" ::: "memory");
        __syncthreads();
        const uint32_t sb = sdyn + stage * STAGE_B;

        #pragma unroll
        for (int half = 0; half < 2; ++half) {
            const uint32_t kb = half * 32;   // 16 bf16 = 32 B
            uint32_t ah[4][4], al[4][4], bh[2][4], bl[2][4];
            #pragma unroll
            for (int mt = 0; mt < 4; ++mt) {
                uint32_t o = aWarp + mt * (16 * ROW_B) + laneA + kb;
                LDSM_X4(ah[mt], sb + OFF_AHI + o);
                LDSM_X4(al[mt], sb + OFF_ALO + o);
            }
            #pragma unroll
            for (int nt2 = 0; nt2 < 2; ++nt2) {
                uint32_t o = bWarp + nt2 * (16 * ROW_B) + laneB + kb;
                LDSM_X4(bh[nt2], sb + OFF_BHI + o);
                LDSM_X4(bl[nt2], sb + OFF_BLO + o);
            }
            #pragma unroll
            for (int mt = 0; mt < 4; ++mt)
                #pragma unroll
                for (int nt = 0; nt < 4; ++nt) {
                    const int n2 = nt >> 1, ns = (nt & 1) * 2;
                    mma_bf16(acc[mt][nt], ah[mt], bh[n2][ns], bh[n2][ns + 1]);
                    mma_bf16(acc[mt][nt], al[mt], bh[n2][ns], bh[n2][ns + 1]);
                    mma_bf16(acc[mt][nt], ah[mt], bl[n2][ns], bl[n2][ns + 1]);
                }
        }
        __syncthreads();
        if (c + NSTG < NCH)
            load_stage(sb, bm, bn, (c + NSTG) * BK, tid);
        stage = (stage + 1) % NSTG;
    }

    // ---- epilogue: direct stores (8 B per lane-quad, rows guarded)
    const int g  = lane >> 2;
    const int tg = lane & 3;
    #pragma unroll
    for (int mt = 0; mt < 4; ++mt) {
        int row0 = bm + warp_m * 64 + mt * 16 + g;
        #pragma unroll
        for (int nt = 0; nt < 4; ++nt) {
            int col = bn + warp_n * 32 + nt * 8 + tg * 2;
            float b0 = bias ? __ldg(&bias[col])     : 0.f;
            float b1 = bias ? __ldg(&bias[col + 1]) : 0.f;
            if (row0 < M) {
                float2 v = make_float2(acc[mt][nt][0] + b0, acc[mt][nt][1] + b1);
                *(float2*)&g_bufH[(size_t)row0 * NI + col] = v;
            }
            if (row0 + 8 < M) {
                float2 v = make_float2(acc[mt][nt][2] + b0, acc[mt][nt][3] + b1);
                *(float2*)&g_bufH[(size_t)(row0 + 8) * NI + col] = v;
            }
        }
    }
}

// ---------------------------------------------------------------- stage 5
__global__ void post_kernel(const float* __restrict__ f,
                            float* __restrict__ out,
                            int m)
{
    int n = blockIdx.x;
    __shared__ float sv[96];
    int t = threadIdx.x;
    if (t < 32 * m) sv[t] = f[(size_t)n * 32 * m + t];
    __syncthreads();
    int o = t >> 5, lane = t & 31;
    float l = g_bufH[(size_t)n * NI + o * 32 + lane];
    float mx = l;
    #pragma unroll
    for (int off = 16; off > 0; off >>= 1)
        mx = fmaxf(mx, __shfl_xor_sync(0xffffffffu, mx, off));
    float e = expf(l - mx);
    float s = e;
    #pragma unroll
    for (int off = 16; off > 0; off >>= 1)
        s += __shfl_xor_sync(0xffffffffu, s, off);
    float attn = e / s;
    #pragma unroll 3
    for (int c = 0; c < m; ++c) {
        float p = attn * sv[lane * m + c];
        #pragma unroll
        for (int off = 16; off > 0; off >>= 1)
            p += __shfl_xor_sync(0xffffffffu, p, off);
        if (lane == 0) out[(size_t)n * 32 * m + o * m + c] = p;
    }
}

// ---------------------------------------------------------------- launch
static void run_type(const float* f, void* const* prm, float* out, int N, int m)
{
    const float* g1    = (const float*)prm[0];
    const float* b1    = (const float*)prm[1];
    const float* w1    = (const float*)prm[2];
    const float* g2    = (const float*)prm[3];
    const float* b2    = (const float*)prm[4];
    const float* w2    = (const float*)prm[5];
    const float* bias2 = (const float*)prm[6];

    dim3 ggrid(NI / BN, (N + BM - 1) / BM);   // n fastest -> A reuse in L2

    prep_kernel<<<N, 1024>>>(f, g1, b1, m);
    splitw_kernel<<<(NI * NI) / 256, 256>>>(w1);
    gemm_bf16_kernel<<<ggrid, 256, DYN_SMEM>>>(nullptr, N);
    mid_ln_kernel<<<N, 1024>>>(g2, b2);
    splitw_kernel<<<(NI * NI) / 256, 256>>>(w2);
    gemm_bf16_kernel<<<ggrid, 256, DYN_SMEM>>>(bias2, N);
    post_kernel<<<N, 1024>>>(f, out, m);
}

extern "C" void kernel_launch(void* const* d_in, const int* in_sizes, int n_in,
                              void* d_out, int out_size)
{
    cudaFuncSetAttribute(gemm_bf16_kernel,
                         cudaFuncAttributeMaxDynamicSharedMemorySize, DYN_SMEM);

    const float* f0 = (const float*)d_in[0];
    const float* f1 = (const float*)d_in[1];
    int N0 = in_sizes[0] / 32;
    int N1 = in_sizes[1] / 96;
    if (N0 > MAXN) N0 = MAXN;
    if (N1 > MAXN) N1 = MAXN;
    float* out = (float*)d_out;

    run_type(f0, d_in + 2, out, N0, 1);
    run_type(f1, d_in + 9, out + (size_t)N0 * 32, N1, 3);
}